// round 6
// baseline (speedup 1.0000x reference)
#include <cuda_runtime.h>

// out[m,b] = sum_n M[m,n,b] * V[n,b]
// M: [2048, 2048, 64] f32 (b contiguous), V: [2048, 64] f32, out: [2048, 64] f32
//
// HBM-streaming kernel, LDG.256 edition:
//   - 128-thread CTAs (8 b-octs x 16 n-slices), grid=1024 (7 CTAs/SM, one wave)
//   - TM=2 m-rows per CTA: one V load feeds FMAs for 2 m-rows
//   - 256-bit loads (ld.v8.b32): warp covers 1024 contiguous bytes/instr
//   - M: evict_first (dead stream)   V: evict_last (pin 512 KB in L2)

#define MV_N     2048
#define MV_MDIM  2048
#define MV_B     64
#define MV_BO    8            // 8 b-octs of 8 floats each
#define MV_TM    2
#define MV_NY    16           // n-slices per CTA

__device__ __forceinline__ void ldg256_stream(const float* p, float* r)
{
    asm("ld.global.nc.L2::evict_first.v8.b32 {%0,%1,%2,%3,%4,%5,%6,%7}, [%8];"
        : "=f"(r[0]), "=f"(r[1]), "=f"(r[2]), "=f"(r[3]),
          "=f"(r[4]), "=f"(r[5]), "=f"(r[6]), "=f"(r[7])
        : "l"(p));
}

__device__ __forceinline__ void ldg256_pin(const float* p, float* r)
{
    asm("ld.global.nc.L2::evict_last.v8.b32 {%0,%1,%2,%3,%4,%5,%6,%7}, [%8];"
        : "=f"(r[0]), "=f"(r[1]), "=f"(r[2]), "=f"(r[3]),
          "=f"(r[4]), "=f"(r[5]), "=f"(r[6]), "=f"(r[7])
        : "l"(p));
}

__global__ __launch_bounds__(128, 7)
void matvec_batched_kernel(const float* __restrict__ M,
                           const float* __restrict__ V,
                           float4* __restrict__ out4)
{
    const int x = threadIdx.x;   // 0..7,  b-oct (8 floats = 32 B)
    const int y = threadIdx.y;   // 0..15, n-slice
    const int m0 = blockIdx.x * MV_TM;

    const float* Ma = M + (size_t)m0 * (size_t)(MV_N * MV_B);
    const float* Mb = Ma + (size_t)(MV_N * MV_B);

    float acc0[8] = {0.f, 0.f, 0.f, 0.f, 0.f, 0.f, 0.f, 0.f};
    float acc1[8] = {0.f, 0.f, 0.f, 0.f, 0.f, 0.f, 0.f, 0.f};

    #pragma unroll 2
    for (int n = y; n < MV_N; n += MV_NY) {
        const int off = n * MV_B + x * 8;
        float v[8], a[8], b[8];
        ldg256_pin(V + off, v);        // V: L2 evict-last (reused chip-wide)
        ldg256_stream(Ma + off, a);    // M: stream-once, evict-first
        ldg256_stream(Mb + off, b);
        #pragma unroll
        for (int i = 0; i < 8; i++) {
            acc0[i] = fmaf(a[i], v[i], acc0[i]);
            acc1[i] = fmaf(b[i], v[i], acc1[i]);
        }
    }

    // Reduce the 16 n-slice partials per b-oct for both m-rows.
    __shared__ float red[MV_TM][MV_NY][MV_BO][8];
    #pragma unroll
    for (int i = 0; i < 8; i++) {
        red[0][y][x][i] = acc0[i];
        red[1][y][x][i] = acc1[i];
    }
    __syncthreads();

    #pragma unroll
    for (int s = MV_NY / 2; s > 0; s >>= 1) {
        if (y < s) {
            #pragma unroll
            for (int t = 0; t < MV_TM; t++)
                #pragma unroll
                for (int i = 0; i < 8; i++)
                    red[t][y][x][i] += red[t][y + s][x][i];
        }
        __syncthreads();
    }

    if (y < MV_TM) {
        // out row (m0+y): 64 floats; this thread writes oct x as two float4s
        float4 lo = make_float4(red[y][0][x][0], red[y][0][x][1],
                                red[y][0][x][2], red[y][0][x][3]);
        float4 hi = make_float4(red[y][0][x][4], red[y][0][x][5],
                                red[y][0][x][6], red[y][0][x][7]);
        const size_t base = (size_t)(m0 + y) * (MV_B / 4) + x * 2;
        out4[base]     = lo;
        out4[base + 1] = hi;
    }
}

extern "C" void kernel_launch(void* const* d_in, const int* in_sizes, int n_in,
                              void* d_out, int out_size)
{
    const float* M = (const float*)d_in[0];
    const float* V = (const float*)d_in[1];
    float4* out4 = (float4*)d_out;

    dim3 block(MV_BO, MV_NY);
    dim3 grid(MV_MDIM / MV_TM);
    matvec_batched_kernel<<<grid, block>>>(M, V, out4);
}

// round 7
// speedup vs baseline: 1.0196x; 1.0196x over previous
#include <cuda_runtime.h>

// out[m,b] = sum_n M[m,n,b] * V[n,b]
// M: [2048, 2048, 64] f32 (b contiguous), V: [2048, 64] f32, out: [2048, 64] f32
//
// HBM-streaming kernel, TM=4 m-rows per CTA:
//   - 128-thread CTAs (16 b-quads x 8 n-slices), grid=512 (all resident, 1 wave)
//   - one V load feeds FMAs for 4 m-rows -> V L2 traffic quartered vs 1-row/CTA
//   - deep unroll for MLP (~20 outstanding LDG.128 per warp)

#define MV_N     2048
#define MV_MDIM  2048
#define MV_B     64
#define MV_BQ    (MV_B / 4)   // 16 float4 per (m,n) row
#define MV_TM    4
#define MV_NY    8            // n-slices per CTA

__global__ __launch_bounds__(128, 4)
void matvec_batched_kernel(const float4* __restrict__ M4,
                           const float4* __restrict__ V4,
                           float4* __restrict__ out4)
{
    const int x = threadIdx.x;   // 0..15, b-quad
    const int y = threadIdx.y;   // 0..7,  n-slice
    const int m0 = blockIdx.x * MV_TM;

    const float4* __restrict__ Mr0 = M4 + (size_t)m0 * (size_t)(MV_N * MV_BQ);
    const float4* __restrict__ Mr1 = Mr0 + (size_t)(MV_N * MV_BQ);
    const float4* __restrict__ Mr2 = Mr1 + (size_t)(MV_N * MV_BQ);
    const float4* __restrict__ Mr3 = Mr2 + (size_t)(MV_N * MV_BQ);

    float4 acc0 = make_float4(0.f, 0.f, 0.f, 0.f);
    float4 acc1 = make_float4(0.f, 0.f, 0.f, 0.f);
    float4 acc2 = make_float4(0.f, 0.f, 0.f, 0.f);
    float4 acc3 = make_float4(0.f, 0.f, 0.f, 0.f);

    #pragma unroll 4
    for (int n = y; n < MV_N; n += MV_NY) {
        const int idx = n * MV_BQ + x;
        const float4 v  = __ldg(&V4[idx]);    // L2-resident, shared by 4 rows
        const float4 a0 = __ldcs(&Mr0[idx]);  // stream-once
        const float4 a1 = __ldcs(&Mr1[idx]);
        const float4 a2 = __ldcs(&Mr2[idx]);
        const float4 a3 = __ldcs(&Mr3[idx]);
        acc0.x = fmaf(a0.x, v.x, acc0.x);
        acc0.y = fmaf(a0.y, v.y, acc0.y);
        acc0.z = fmaf(a0.z, v.z, acc0.z);
        acc0.w = fmaf(a0.w, v.w, acc0.w);
        acc1.x = fmaf(a1.x, v.x, acc1.x);
        acc1.y = fmaf(a1.y, v.y, acc1.y);
        acc1.z = fmaf(a1.z, v.z, acc1.z);
        acc1.w = fmaf(a1.w, v.w, acc1.w);
        acc2.x = fmaf(a2.x, v.x, acc2.x);
        acc2.y = fmaf(a2.y, v.y, acc2.y);
        acc2.z = fmaf(a2.z, v.z, acc2.z);
        acc2.w = fmaf(a2.w, v.w, acc2.w);
        acc3.x = fmaf(a3.x, v.x, acc3.x);
        acc3.y = fmaf(a3.y, v.y, acc3.y);
        acc3.z = fmaf(a3.z, v.z, acc3.z);
        acc3.w = fmaf(a3.w, v.w, acc3.w);
    }

    // Reduce the 8 n-slice partials per b-quad for all 4 m-rows.
    __shared__ float4 red[MV_TM][MV_NY][16];
    red[0][y][x] = acc0;
    red[1][y][x] = acc1;
    red[2][y][x] = acc2;
    red[3][y][x] = acc3;
    __syncthreads();

    #pragma unroll
    for (int s = MV_NY / 2; s > 0; s >>= 1) {
        if (y < s) {
            #pragma unroll
            for (int t = 0; t < MV_TM; t++) {
                float4 o = red[t][y + s][x];
                float4 a = red[t][y][x];
                a.x += o.x; a.y += o.y; a.z += o.z; a.w += o.w;
                red[t][y][x] = a;
            }
        }
        __syncthreads();
    }

    if (y < MV_TM) {
        out4[(size_t)(m0 + y) * MV_BQ + x] = red[y][0][x];
    }
}

extern "C" void kernel_launch(void* const* d_in, const int* in_sizes, int n_in,
                              void* d_out, int out_size)
{
    const float4* M4 = (const float4*)d_in[0];
    const float4* V4 = (const float4*)d_in[1];
    float4* out4 = (float4*)d_out;

    dim3 block(16, MV_NY);
    dim3 grid(MV_MDIM / MV_TM);
    matvec_batched_kernel<<<grid, block>>>(M4, V4, out4);
}

// round 8
// speedup vs baseline: 1.0292x; 1.0095x over previous
#include <cuda_runtime.h>

// out[m,b] = sum_n M[m,n,b] * V[n,b]
// M: [2048, 2048, 64] f32 (b contiguous), V: [2048, 64] f32, out: [2048, 64] f32
//
// HBM-streaming kernel, deep-MLP edition:
//   - 64-thread CTAs (16 b-quads x 4 n-slices), grid=1024, TM=2
//   - 7 CTAs/SM resident (reg cap 146) -> single wave, 14 warps/SM
//   - unroll 8: ~24 front-batched LDG.128 per thread for max MLP
//   - one V load feeds FMAs for 2 m-rows

#define MV_N     2048
#define MV_MDIM  2048
#define MV_B     64
#define MV_BQ    (MV_B / 4)   // 16 float4 per (m,n) row
#define MV_TM    2
#define MV_NY    4            // n-slices per CTA

__global__ __launch_bounds__(64, 7)
void matvec_batched_kernel(const float4* __restrict__ M4,
                           const float4* __restrict__ V4,
                           float4* __restrict__ out4)
{
    const int x = threadIdx.x;   // 0..15, b-quad
    const int y = threadIdx.y;   // 0..3,  n-slice
    const int m0 = blockIdx.x * MV_TM;

    const float4* __restrict__ Ma = M4 + (size_t)m0 * (size_t)(MV_N * MV_BQ);
    const float4* __restrict__ Mb = Ma + (size_t)(MV_N * MV_BQ);

    float4 acc0 = make_float4(0.f, 0.f, 0.f, 0.f);
    float4 acc1 = make_float4(0.f, 0.f, 0.f, 0.f);

    #pragma unroll 8
    for (int n = y; n < MV_N; n += MV_NY) {
        const int idx = n * MV_BQ + x;
        const float4 v = __ldg(&V4[idx]);
        const float4 a = __ldcs(&Ma[idx]);
        const float4 b = __ldcs(&Mb[idx]);
        acc0.x = fmaf(a.x, v.x, acc0.x);
        acc0.y = fmaf(a.y, v.y, acc0.y);
        acc0.z = fmaf(a.z, v.z, acc0.z);
        acc0.w = fmaf(a.w, v.w, acc0.w);
        acc1.x = fmaf(b.x, v.x, acc1.x);
        acc1.y = fmaf(b.y, v.y, acc1.y);
        acc1.z = fmaf(b.z, v.z, acc1.z);
        acc1.w = fmaf(b.w, v.w, acc1.w);
    }

    // Reduce the 4 n-slice partials per b-quad for both m-rows.
    __shared__ float4 red[MV_TM][MV_NY][16];
    red[0][y][x] = acc0;
    red[1][y][x] = acc1;
    __syncthreads();

    #pragma unroll
    for (int s = MV_NY / 2; s > 0; s >>= 1) {
        if (y < s) {
            #pragma unroll
            for (int t = 0; t < MV_TM; t++) {
                float4 o = red[t][y + s][x];
                float4 a0 = red[t][y][x];
                a0.x += o.x; a0.y += o.y; a0.z += o.z; a0.w += o.w;
                red[t][y][x] = a0;
            }
        }
        __syncthreads();
    }

    if (y < MV_TM) {
        out4[(size_t)(m0 + y) * MV_BQ + x] = red[y][0][x];
    }
}

extern "C" void kernel_launch(void* const* d_in, const int* in_sizes, int n_in,
                              void* d_out, int out_size)
{
    const float4* M4 = (const float4*)d_in[0];
    const float4* V4 = (const float4*)d_in[1];
    float4* out4 = (float4*)d_out;

    dim3 block(16, MV_NY);
    dim3 grid(MV_MDIM / MV_TM);
    matvec_batched_kernel<<<grid, block>>>(M4, V4, out4);
}